// round 3
// baseline (speedup 1.0000x reference)
#include <cuda_runtime.h>
#include <math.h>

// Fixed problem shapes
#define BB   4
#define SS   4096
#define DDIM 512
#define HH   2048
#define LL   3
#define MMR  (BB*SS)      // 16384 rows
#define CHK  128          // scan chunk length (per-thread serial)
#define NCH  (SS/CHK)     // 32 chunks per sequence

// ---------------- scratch (static device arrays; no allocation) --------------
__device__ float g_xbuf[MMR*DDIM];   // residual stream x
__device__ float g_gin [MMR*DDIM];   // gru_in (LN output)
__device__ float g_k   [MMR*DDIM];   // k -> c  (also dwconv + mlp_in scratch)
__device__ float g_a   [MMR*DDIM];   // a -> v
__device__ float g_h1  [MMR*HH];     // MLP hidden
__device__ float g_P [BB*DDIM*NCH];
__device__ float g_V [BB*DDIM*NCH];
__device__ float g_Hi[BB*DDIM*NCH];

// ---------------- depthwise causal conv (K=4, cross-correlation) -------------
__global__ void dwconv_kernel(const float* __restrict__ x,
                              const float* __restrict__ w,
                              const float* __restrict__ wb,
                              float* __restrict__ out)
{
    int idx = blockIdx.x * blockDim.x + threadIdx.x;   // b*S*D + s*D + c
    if (idx >= MMR*DDIM) return;
    int c = idx % DDIM;
    int bs = idx / DDIM;
    int s = bs % SS;
    float acc = wb[c];
    #pragma unroll
    for (int k = 0; k < 4; k++) {
        int sp = s + k - 3;
        if (sp >= 0) acc += w[c*4 + k] * x[idx + (k-3)*DDIM];
    }
    out[idx] = acc;
}

// ---------------- SGEMM 128x128x8, 8x8 micro, 256 threads --------------------
// C[m,n] = sum_k A[m,k]*B(k,n);   TRANSB: B stored [N,K] (B[n*K+k])
template<bool TRANSB>
__global__ void __launch_bounds__(256)
sgemm_kernel(const float* __restrict__ A, const float* __restrict__ B,
             float* __restrict__ C, int M, int N, int K,
             const float* __restrict__ bias, const float* __restrict__ resid,
             int dorelu)
{
    __shared__ float As[8][128];
    __shared__ float Bs[8][128];
    const int tid = threadIdx.x;
    const int bm = blockIdx.y * 128;
    const int bn = blockIdx.x * 128;
    const int tx = tid & 15;        // 0..15 -> 8 cols each
    const int ty = tid >> 4;        // 0..15 -> 8 rows each
    const int ar  = tid >> 1;       // 0..127
    const int ac  = (tid & 1) * 4;  // 0 or 4
    const int br  = tid >> 5;       // 0..7
    const int bc  = (tid & 31) * 4; // 0..124

    float acc[8][8];
    #pragma unroll
    for (int i = 0; i < 8; i++)
        #pragma unroll
        for (int j = 0; j < 8; j++) acc[i][j] = 0.f;

    for (int k0 = 0; k0 < K; k0 += 8) {
        float4 av = *(const float4*)&A[(size_t)(bm + ar)*K + k0 + ac];
        As[ac+0][ar] = av.x; As[ac+1][ar] = av.y;
        As[ac+2][ar] = av.z; As[ac+3][ar] = av.w;
        if (TRANSB) {
            float4 bv = *(const float4*)&B[(size_t)(bn + ar)*K + k0 + ac];
            Bs[ac+0][ar] = bv.x; Bs[ac+1][ar] = bv.y;
            Bs[ac+2][ar] = bv.z; Bs[ac+3][ar] = bv.w;
        } else {
            float4 bv = *(const float4*)&B[(size_t)(k0 + br)*N + bn + bc];
            *(float4*)&Bs[br][bc] = bv;
        }
        __syncthreads();
        #pragma unroll
        for (int kk = 0; kk < 8; kk++) {
            float a[8], b[8];
            *(float4*)(a)   = *(const float4*)&As[kk][ty*8];
            *(float4*)(a+4) = *(const float4*)&As[kk][ty*8+4];
            *(float4*)(b)   = *(const float4*)&Bs[kk][tx*8];
            *(float4*)(b+4) = *(const float4*)&Bs[kk][tx*8+4];
            #pragma unroll
            for (int i = 0; i < 8; i++)
                #pragma unroll
                for (int j = 0; j < 8; j++)
                    acc[i][j] = fmaf(a[i], b[j], acc[i][j]);
        }
        __syncthreads();
    }

    #pragma unroll
    for (int i = 0; i < 8; i++) {
        int row = bm + ty*8 + i;
        #pragma unroll
        for (int j = 0; j < 8; j++) {
            int col = bn + tx*8 + j;
            float v = acc[i][j];
            if (bias)   v += bias[col];
            if (dorelu) v = fmaxf(v, 0.f);
            if (resid)  v += resid[(size_t)row*N + col];
            C[(size_t)row*N + col] = v;
        }
    }
}

// ---------------- LayerNorm over last dim (512), warp-per-row ---------------
__global__ void ln_kernel(const float* __restrict__ in, float* __restrict__ out,
                          const float* __restrict__ g, const float* __restrict__ b)
{
    int warp = threadIdx.x >> 5, lane = threadIdx.x & 31;
    int row = blockIdx.x * 8 + warp;
    const float* p = in + (size_t)row * DDIM;
    float vals[16];
    float s = 0.f;
    #pragma unroll
    for (int i = 0; i < 16; i++) { vals[i] = p[lane + i*32]; s += vals[i]; }
    #pragma unroll
    for (int o = 16; o > 0; o >>= 1) s += __shfl_xor_sync(0xffffffff, s, o);
    float mean = s * (1.f/DDIM);
    float vs = 0.f;
    #pragma unroll
    for (int i = 0; i < 16; i++) { float d = vals[i]-mean; vs += d*d; }
    #pragma unroll
    for (int o = 16; o > 0; o >>= 1) vs += __shfl_xor_sync(0xffffffff, vs, o);
    float inv = rsqrtf(vs * (1.f/DDIM) + 1e-5f);
    float* q = out + (size_t)row * DDIM;
    #pragma unroll
    for (int i = 0; i < 16; i++) {
        int c = lane + i*32;
        q[c] = (vals[i]-mean) * inv * g[c] + b[c];
    }
}

// ---------------- scan pass1 (fused gating): k,a -> c,v ; chunk carries -----
// c = sigmoid(-k), v = sigmoid(k)*g(a), g(a) = a>=0 ? a+0.5 : sigmoid(a)
// Writes c,v back over k,a (for pass3), and per-chunk (P = prod c, V).
__global__ void scan_pass1(float* __restrict__ kb, float* __restrict__ ab,
                           float* __restrict__ Pb, float* __restrict__ Vb)
{
    int gid = blockIdx.x * blockDim.x + threadIdx.x;   // b*(NCH*D) + chunk*D + d
    int b = gid / (DDIM*NCH);
    int r = gid - b*(DDIM*NCH);
    int chunk = r / DDIM;
    int d = r - chunk*DDIM;
    size_t base = ((size_t)b*SS + (size_t)chunk*CHK)*DDIM + d;
    float p = 1.f, v = 0.f;
    for (int i = 0; i < CHK; i++) {
        size_t o = base + (size_t)i*DDIM;
        float k = kb[o];
        float a = ab[o];
        float e = __expf(k);
        float ci = 1.f / (1.f + e);           // sigmoid(-k)
        float zi = e * ci;                    // sigmoid(k)
        float gg = (a >= 0.f) ? (a + 0.5f) : (1.f / (1.f + __expf(-a)));
        float vi = zi * gg;
        kb[o] = ci;
        ab[o] = vi;
        v = fmaf(ci, v, vi);
        p *= ci;
    }
    int ch = (b*DDIM + d)*NCH + chunk;
    Pb[ch] = p; Vb[ch] = v;
}

// pass2: per-channel serial scan over 32 chunk carries
__global__ void scan_pass2(const float* __restrict__ Pb, const float* __restrict__ Vb,
                           float* __restrict__ Hib)
{
    int ch = blockIdx.x * blockDim.x + threadIdx.x;    // 0..B*D-1
    if (ch >= BB*DDIM) return;
    float h = 0.5f;
    #pragma unroll
    for (int c = 0; c < NCH; c++) {
        Hib[ch*NCH + c] = h;
        h = fmaf(Pb[ch*NCH + c], h, Vb[ch*NCH + c]);
    }
}

// pass3: re-scan applying carry, x += h (in place on xbuf)
__global__ void scan_pass3(const float* __restrict__ cb, const float* __restrict__ vb,
                           const float* __restrict__ Hib, float* __restrict__ xb)
{
    int gid = blockIdx.x * blockDim.x + threadIdx.x;
    int b = gid / (DDIM*NCH);
    int r = gid - b*(DDIM*NCH);
    int chunk = r / DDIM;
    int d = r - chunk*DDIM;
    size_t base = ((size_t)b*SS + (size_t)chunk*CHK)*DDIM + d;
    float h = Hib[(b*DDIM + d)*NCH + chunk];
    for (int i = 0; i < CHK; i++) {
        size_t o = base + (size_t)i*DDIM;
        h = fmaf(cb[o], h, vb[o]);
        xb[o] += h;
    }
}

// -------------------------------- launch ------------------------------------
extern "C" void kernel_launch(void* const* d_in, const int* in_sizes, int n_in,
                              void* d_out, int out_size)
{
    const float* x     = (const float*)d_in[0];
    const float* dw_w  = (const float*)d_in[1];
    const float* dw_b  = (const float*)d_in[2];
    const float* pw_w  = (const float*)d_in[3];
    const float* pw_b  = (const float*)d_in[4];
    const float* ln1_g = (const float*)d_in[5];
    const float* ln1_b = (const float*)d_in[6];
    const float* Wz    = (const float*)d_in[7];
    const float* Wh    = (const float*)d_in[8];
    const float* lng   = (const float*)d_in[9];
    const float* lnb   = (const float*)d_in[10];
    const float* ln2_g = (const float*)d_in[11];
    const float* ln2_b = (const float*)d_in[12];
    const float* W1    = (const float*)d_in[13];
    const float* b1    = (const float*)d_in[14];
    const float* W2    = (const float*)d_in[15];
    const float* b2    = (const float*)d_in[16];
    float* out = (float*)d_out;

    float *xbuf, *gin, *kb, *ab, *hb, *Pb, *Vb, *Hib;
    cudaGetSymbolAddress((void**)&xbuf, g_xbuf);
    cudaGetSymbolAddress((void**)&gin,  g_gin);
    cudaGetSymbolAddress((void**)&kb,   g_k);
    cudaGetSymbolAddress((void**)&ab,   g_a);
    cudaGetSymbolAddress((void**)&hb,   g_h1);
    cudaGetSymbolAddress((void**)&Pb,   g_P);
    cudaGetSymbolAddress((void**)&Vb,   g_V);
    cudaGetSymbolAddress((void**)&Hib,  g_Hi);

    const int NELT = MMR*DDIM;
    dim3 eltGrid((NELT + 255)/256);

    // 1) depthwise conv -> kb
    dwconv_kernel<<<eltGrid, 256>>>(x, dw_w, dw_b, kb);

    // 2) pointwise conv (B = pw_w[o,c] transposed) + pw_b + residual x -> xbuf
    sgemm_kernel<true><<<dim3(DDIM/128, MMR/128), 256>>>(
        kb, pw_w, xbuf, MMR, DDIM, DDIM, pw_b, x, 0);

    // 3) gru_in = LN(xbuf, ln1)
    ln_kernel<<<MMR/8, 256>>>(xbuf, gin, ln1_g, ln1_b);

    // 4) GRU layers
    for (int l = 0; l < LL; l++) {
        sgemm_kernel<false><<<dim3(DDIM/128, MMR/128), 256>>>(
            gin, Wz + (size_t)l*DDIM*DDIM, kb, MMR, DDIM, DDIM, nullptr, nullptr, 0);
        sgemm_kernel<false><<<dim3(DDIM/128, MMR/128), 256>>>(
            gin, Wh + (size_t)l*DDIM*DDIM, ab, MMR, DDIM, DDIM, nullptr, nullptr, 0);
        scan_pass1<<<(BB*DDIM*NCH)/256, 256>>>(kb, ab, Pb, Vb);
        scan_pass2<<<(BB*DDIM + 255)/256, 256>>>(Pb, Vb, Hib);
        scan_pass3<<<(BB*DDIM*NCH)/256, 256>>>(kb, ab, Hib, xbuf);
        ln_kernel<<<MMR/8, 256>>>(xbuf, gin, lng + l*DDIM, lnb + l*DDIM);
    }

    // 5) mlp_in = LN(gin, ln2) -> kb
    ln_kernel<<<MMR/8, 256>>>(gin, kb, ln2_g, ln2_b);

    // 6) hidden = relu(mlp_in @ W1 + b1) -> hb
    sgemm_kernel<false><<<dim3(HH/128, MMR/128), 256>>>(
        kb, W1, hb, MMR, HH, DDIM, b1, nullptr, 1);

    // 7) out = hidden @ W2 + b2 + xbuf
    sgemm_kernel<false><<<dim3(DDIM/128, MMR/128), 256>>>(
        hb, W2, out, MMR, DDIM, HH, b2, xbuf, 0);
}

// round 5
// speedup vs baseline: 1.4013x; 1.4013x over previous
#include <cuda_runtime.h>
#include <cstdint>
#include <math.h>
#include <mma.h>
using namespace nvcuda;

// Fixed problem shapes
#define BB   4
#define SS   4096
#define DDIM 512
#define HH   2048
#define LL   3
#define MMR  (BB*SS)      // 16384 rows
#define CHK  128          // scan chunk length (per-thread serial)
#define NCH  (SS/CHK)     // 32 chunks per sequence

#define KTILE 32
#define ASTR  40          // A smem stride (floats), mult of 4
#define BSTR  136         // B smem stride (non-trans, [k][n])
#define BTSTR 40          // B smem stride (trans, [n][k])
#define ASZ   (128*ASTR)  // 5120 floats
#define BSZ_MAX (128*BTSTR) // 5120 floats (>= 32*BSTR=4352)
#define SMEMSZ ((2*ASZ + 2*BSZ_MAX)*4)   // 81920 bytes

// ---------------- scratch (static device arrays; no allocation) --------------
__device__ float g_xbuf[MMR*DDIM];   // residual stream x
__device__ float g_gin [MMR*DDIM];   // gru_in (LN output)
__device__ float g_k   [MMR*DDIM];   // k -> c  (also dwconv + mlp_in scratch)
__device__ float g_a   [MMR*DDIM];   // a -> v
__device__ float g_h1  [MMR*HH];     // MLP hidden
__device__ float g_P [BB*DDIM*NCH];
__device__ float g_V [BB*DDIM*NCH];
__device__ float g_Hi[BB*DDIM*NCH];

// ---------------- depthwise causal conv (K=4, cross-correlation) -------------
__global__ void dwconv_kernel(const float* __restrict__ x,
                              const float* __restrict__ w,
                              const float* __restrict__ wb,
                              float* __restrict__ out)
{
    int idx = blockIdx.x * blockDim.x + threadIdx.x;   // b*S*D + s*D + c
    if (idx >= MMR*DDIM) return;
    int c = idx % DDIM;
    int bs = idx / DDIM;
    int s = bs % SS;
    float acc = wb[c];
    #pragma unroll
    for (int k = 0; k < 4; k++) {
        int sp = s + k - 3;
        if (sp >= 0) acc += w[c*4 + k] * x[idx + (k-3)*DDIM];
    }
    out[idx] = acc;
}

// ---------------- TF32 tensor-core GEMM, 128x128x32, 8 warps -----------------
// C[m,n] = sum_k A[m,k]*B(k,n);   TRANSB: B stored [N,K] (B[n*K+k])
__device__ __forceinline__ void cpasync16(float* dst, const float* src)
{
    unsigned int d = (unsigned int)__cvta_generic_to_shared(dst);
    asm volatile("cp.async.cg.shared.global [%0], [%1], 16;\n" :: "r"(d), "l"(src));
}

template<bool TRANSB>
__global__ void __launch_bounds__(256)
tgemm_kernel(const float* __restrict__ A, const float* __restrict__ B,
             float* __restrict__ C, int M, int N, int K,
             const float* __restrict__ bias, const float* __restrict__ resid,
             int dorelu)
{
    extern __shared__ float sm[];
    float* Asm[2] = { sm, sm + ASZ };
    float* Bsm[2] = { sm + 2*ASZ, sm + 2*ASZ + BSZ_MAX };
    float* Cs = sm;   // reused for epilogue (64KB < 80KB)

    const int tid = threadIdx.x;
    const int wid = tid >> 5;
    const int bm = blockIdx.y * 128;
    const int bn = blockIdx.x * 128;
    const int wm = (wid >> 2) * 64;   // warp grid 2(m) x 4(n)
    const int wn = (wid & 3) * 32;

    wmma::fragment<wmma::accumulator, 16, 16, 8, float> acc[4][2];
    #pragma unroll
    for (int i = 0; i < 4; i++)
        #pragma unroll
        for (int j = 0; j < 2; j++) wmma::fill_fragment(acc[i][j], 0.f);

    // ---- tile loaders (cp.async) ----
    auto loadA = [&](int buf, int k0) {
        #pragma unroll
        for (int i = 0; i < 4; i++) {
            int idx = tid + i*256;          // 1024 float4 = 128 rows x 8 f4
            int r = idx >> 3, c4 = (idx & 7) * 4;
            cpasync16(Asm[buf] + r*ASTR + c4, A + (size_t)(bm + r)*K + k0 + c4);
        }
    };
    auto loadB = [&](int buf, int k0) {
        if (TRANSB) {
            #pragma unroll
            for (int i = 0; i < 4; i++) {
                int idx = tid + i*256;      // 128 rows (n) x 8 f4 (k)
                int r = idx >> 3, c4 = (idx & 7) * 4;
                cpasync16(Bsm[buf] + r*BTSTR + c4, B + (size_t)(bn + r)*K + k0 + c4);
            }
        } else {
            #pragma unroll
            for (int i = 0; i < 4; i++) {
                int idx = tid + i*256;      // 32 rows (k) x 32 f4 (n)
                int r = idx >> 5, c4 = (idx & 31) * 4;
                cpasync16(Bsm[buf] + r*BSTR + c4, B + (size_t)(k0 + r)*N + bn + c4);
            }
        }
    };

    const int nk = K / KTILE;
    loadA(0, 0); loadB(0, 0);
    asm volatile("cp.async.commit_group;\n");

    for (int kt = 0; kt < nk; kt++) {
        if (kt + 1 < nk) {
            loadA((kt+1)&1, (kt+1)*KTILE);
            loadB((kt+1)&1, (kt+1)*KTILE);
            asm volatile("cp.async.commit_group;\n");
            asm volatile("cp.async.wait_group 1;\n");
        } else {
            asm volatile("cp.async.wait_group 0;\n");
        }
        __syncthreads();

        const float* a = Asm[kt&1];
        const float* b = Bsm[kt&1];
        #pragma unroll
        for (int ks = 0; ks < 4; ks++) {
            const int kk = ks * 8;
            wmma::fragment<wmma::matrix_a, 16, 16, 8, wmma::precision::tf32, wmma::row_major> af[4];
            #pragma unroll
            for (int i = 0; i < 4; i++) {
                wmma::load_matrix_sync(af[i], a + (wm + i*16)*ASTR + kk, ASTR);
                #pragma unroll
                for (int e = 0; e < af[i].num_elements; e++)
                    af[i].x[e] = wmma::__float_to_tf32(af[i].x[e]);
            }
            if constexpr (TRANSB) {
                wmma::fragment<wmma::matrix_b, 16, 16, 8, wmma::precision::tf32, wmma::col_major> bf[2];
                #pragma unroll
                for (int j = 0; j < 2; j++) {
                    wmma::load_matrix_sync(bf[j], b + (wn + j*16)*BTSTR + kk, BTSTR);
                    #pragma unroll
                    for (int e = 0; e < bf[j].num_elements; e++)
                        bf[j].x[e] = wmma::__float_to_tf32(bf[j].x[e]);
                }
                #pragma unroll
                for (int i = 0; i < 4; i++)
                    #pragma unroll
                    for (int j = 0; j < 2; j++)
                        wmma::mma_sync(acc[i][j], af[i], bf[j], acc[i][j]);
            } else {
                wmma::fragment<wmma::matrix_b, 16, 16, 8, wmma::precision::tf32, wmma::row_major> bf[2];
                #pragma unroll
                for (int j = 0; j < 2; j++) {
                    wmma::load_matrix_sync(bf[j], b + kk*BSTR + wn + j*16, BSTR);
                    #pragma unroll
                    for (int e = 0; e < bf[j].num_elements; e++)
                        bf[j].x[e] = wmma::__float_to_tf32(bf[j].x[e]);
                }
                #pragma unroll
                for (int i = 0; i < 4; i++)
                    #pragma unroll
                    for (int j = 0; j < 2; j++)
                        wmma::mma_sync(acc[i][j], af[i], bf[j], acc[i][j]);
            }
        }
        __syncthreads();
    }

    // ---- epilogue: frags -> smem -> fused bias/relu/resid -> C ----
    #pragma unroll
    for (int i = 0; i < 4; i++)
        #pragma unroll
        for (int j = 0; j < 2; j++)
            wmma::store_matrix_sync(Cs + (wm + i*16)*128 + wn + j*16, acc[i][j],
                                    128, wmma::mem_row_major);
    __syncthreads();

    #pragma unroll
    for (int it = 0; it < 16; it++) {
        int idx = tid + it*256;             // 4096 float4 over 128x128
        int r = idx >> 5, c4 = (idx & 31) * 4;
        float4 v = *(float4*)&Cs[r*128 + c4];
        int row = bm + r, col = bn + c4;
        if (bias) {
            float4 bv = *(const float4*)&bias[col];
            v.x += bv.x; v.y += bv.y; v.z += bv.z; v.w += bv.w;
        }
        if (dorelu) {
            v.x = fmaxf(v.x, 0.f); v.y = fmaxf(v.y, 0.f);
            v.z = fmaxf(v.z, 0.f); v.w = fmaxf(v.w, 0.f);
        }
        if (resid) {
            float4 rv = *(const float4*)&resid[(size_t)row*N + col];
            v.x += rv.x; v.y += rv.y; v.z += rv.z; v.w += rv.w;
        }
        *(float4*)&C[(size_t)row*N + col] = v;
    }
}

// ---------------- LayerNorm over last dim (512), warp-per-row ---------------
__global__ void ln_kernel(const float* __restrict__ in, float* __restrict__ out,
                          const float* __restrict__ g, const float* __restrict__ b)
{
    int warp = threadIdx.x >> 5, lane = threadIdx.x & 31;
    int row = blockIdx.x * 8 + warp;
    const float* p = in + (size_t)row * DDIM;
    float vals[16];
    float s = 0.f;
    #pragma unroll
    for (int i = 0; i < 16; i++) { vals[i] = p[lane + i*32]; s += vals[i]; }
    #pragma unroll
    for (int o = 16; o > 0; o >>= 1) s += __shfl_xor_sync(0xffffffff, s, o);
    float mean = s * (1.f/DDIM);
    float vs = 0.f;
    #pragma unroll
    for (int i = 0; i < 16; i++) { float d = vals[i]-mean; vs += d*d; }
    #pragma unroll
    for (int o = 16; o > 0; o >>= 1) vs += __shfl_xor_sync(0xffffffff, vs, o);
    float inv = rsqrtf(vs * (1.f/DDIM) + 1e-5f);
    float* q = out + (size_t)row * DDIM;
    #pragma unroll
    for (int i = 0; i < 16; i++) {
        int c = lane + i*32;
        q[c] = (vals[i]-mean) * inv * g[c] + b[c];
    }
}

// ---------------- scan pass1 (fused gating): k,a -> c,v ; chunk carries -----
__global__ void scan_pass1(float* __restrict__ kb, float* __restrict__ ab,
                           float* __restrict__ Pb, float* __restrict__ Vb)
{
    int gid = blockIdx.x * blockDim.x + threadIdx.x;   // b*(NCH*D) + chunk*D + d
    int b = gid / (DDIM*NCH);
    int r = gid - b*(DDIM*NCH);
    int chunk = r / DDIM;
    int d = r - chunk*DDIM;
    size_t base = ((size_t)b*SS + (size_t)chunk*CHK)*DDIM + d;
    float p = 1.f, v = 0.f;
    for (int i = 0; i < CHK; i++) {
        size_t o = base + (size_t)i*DDIM;
        float k = kb[o];
        float a = ab[o];
        float e = __expf(k);
        float ci = 1.f / (1.f + e);           // sigmoid(-k)
        float zi = e * ci;                    // sigmoid(k)
        float gg = (a >= 0.f) ? (a + 0.5f) : (1.f / (1.f + __expf(-a)));
        float vi = zi * gg;
        kb[o] = ci;
        ab[o] = vi;
        v = fmaf(ci, v, vi);
        p *= ci;
    }
    int ch = (b*DDIM + d)*NCH + chunk;
    Pb[ch] = p; Vb[ch] = v;
}

// pass2: per-channel serial scan over 32 chunk carries
__global__ void scan_pass2(const float* __restrict__ Pb, const float* __restrict__ Vb,
                           float* __restrict__ Hib)
{
    int ch = blockIdx.x * blockDim.x + threadIdx.x;    // 0..B*D-1
    if (ch >= BB*DDIM) return;
    float h = 0.5f;
    #pragma unroll
    for (int c = 0; c < NCH; c++) {
        Hib[ch*NCH + c] = h;
        h = fmaf(Pb[ch*NCH + c], h, Vb[ch*NCH + c]);
    }
}

// pass3: re-scan applying carry, x += h (in place on xbuf)
__global__ void scan_pass3(const float* __restrict__ cb, const float* __restrict__ vb,
                           const float* __restrict__ Hib, float* __restrict__ xb)
{
    int gid = blockIdx.x * blockDim.x + threadIdx.x;
    int b = gid / (DDIM*NCH);
    int r = gid - b*(DDIM*NCH);
    int chunk = r / DDIM;
    int d = r - chunk*DDIM;
    size_t base = ((size_t)b*SS + (size_t)chunk*CHK)*DDIM + d;
    float h = Hib[(b*DDIM + d)*NCH + chunk];
    for (int i = 0; i < CHK; i++) {
        size_t o = base + (size_t)i*DDIM;
        h = fmaf(cb[o], h, vb[o]);
        xb[o] += h;
    }
}

// -------------------------------- launch ------------------------------------
extern "C" void kernel_launch(void* const* d_in, const int* in_sizes, int n_in,
                              void* d_out, int out_size)
{
    const float* x     = (const float*)d_in[0];
    const float* dw_w  = (const float*)d_in[1];
    const float* dw_b  = (const float*)d_in[2];
    const float* pw_w  = (const float*)d_in[3];
    const float* pw_b  = (const float*)d_in[4];
    const float* ln1_g = (const float*)d_in[5];
    const float* ln1_b = (const float*)d_in[6];
    const float* Wz    = (const float*)d_in[7];
    const float* Wh    = (const float*)d_in[8];
    const float* lng   = (const float*)d_in[9];
    const float* lnb   = (const float*)d_in[10];
    const float* ln2_g = (const float*)d_in[11];
    const float* ln2_b = (const float*)d_in[12];
    const float* W1    = (const float*)d_in[13];
    const float* b1    = (const float*)d_in[14];
    const float* W2    = (const float*)d_in[15];
    const float* b2    = (const float*)d_in[16];
    float* out = (float*)d_out;

    float *xbuf, *gin, *kb, *ab, *hb, *Pb, *Vb, *Hib;
    cudaGetSymbolAddress((void**)&xbuf, g_xbuf);
    cudaGetSymbolAddress((void**)&gin,  g_gin);
    cudaGetSymbolAddress((void**)&kb,   g_k);
    cudaGetSymbolAddress((void**)&ab,   g_a);
    cudaGetSymbolAddress((void**)&hb,   g_h1);
    cudaGetSymbolAddress((void**)&Pb,   g_P);
    cudaGetSymbolAddress((void**)&Vb,   g_V);
    cudaGetSymbolAddress((void**)&Hib,  g_Hi);

    cudaFuncSetAttribute(tgemm_kernel<true>,
        cudaFuncAttributeMaxDynamicSharedMemorySize, SMEMSZ);
    cudaFuncSetAttribute(tgemm_kernel<false>,
        cudaFuncAttributeMaxDynamicSharedMemorySize, SMEMSZ);

    const int NELT = MMR*DDIM;
    dim3 eltGrid((NELT + 255)/256);

    // 1) depthwise conv -> kb
    dwconv_kernel<<<eltGrid, 256>>>(x, dw_w, dw_b, kb);

    // 2) pointwise conv (B = pw_w[o,c] transposed) + pw_b + residual x -> xbuf
    tgemm_kernel<true><<<dim3(DDIM/128, MMR/128), 256, SMEMSZ>>>(
        kb, pw_w, xbuf, MMR, DDIM, DDIM, pw_b, x, 0);

    // 3) gru_in = LN(xbuf, ln1)
    ln_kernel<<<MMR/8, 256>>>(xbuf, gin, ln1_g, ln1_b);

    // 4) GRU layers
    for (int l = 0; l < LL; l++) {
        tgemm_kernel<false><<<dim3(DDIM/128, MMR/128), 256, SMEMSZ>>>(
            gin, Wz + (size_t)l*DDIM*DDIM, kb, MMR, DDIM, DDIM, nullptr, nullptr, 0);
        tgemm_kernel<false><<<dim3(DDIM/128, MMR/128), 256, SMEMSZ>>>(
            gin, Wh + (size_t)l*DDIM*DDIM, ab, MMR, DDIM, DDIM, nullptr, nullptr, 0);
        scan_pass1<<<(BB*DDIM*NCH)/256, 256>>>(kb, ab, Pb, Vb);
        scan_pass2<<<(BB*DDIM + 255)/256, 256>>>(Pb, Vb, Hib);
        scan_pass3<<<(BB*DDIM*NCH)/256, 256>>>(kb, ab, Hib, xbuf);
        ln_kernel<<<MMR/8, 256>>>(xbuf, gin, lng + l*DDIM, lnb + l*DDIM);
    }

    // 5) mlp_in = LN(gin, ln2) -> kb
    ln_kernel<<<MMR/8, 256>>>(gin, kb, ln2_g, ln2_b);

    // 6) hidden = relu(mlp_in @ W1 + b1) -> hb
    tgemm_kernel<false><<<dim3(HH/128, MMR/128), 256, SMEMSZ>>>(
        kb, W1, hb, MMR, HH, DDIM, b1, nullptr, 1);

    // 7) out = hidden @ W2 + b2 + xbuf
    tgemm_kernel<false><<<dim3(DDIM/128, MMR/128), 256, SMEMSZ>>>(
        hb, W2, out, MMR, DDIM, HH, b2, xbuf, 0);
}

// round 6
// speedup vs baseline: 1.6100x; 1.1489x over previous
#include <cuda_runtime.h>
#include <cstdint>
#include <math.h>
#include <mma.h>
using namespace nvcuda;

// Fixed problem shapes
#define BB   4
#define SS   4096
#define DDIM 512
#define HH   2048
#define LL   3
#define MMR  (BB*SS)      // 16384 rows
#define CHK  128          // scan chunk length (per-thread serial)
#define NCH  (SS/CHK)     // 32 chunks per sequence

// GEMM tiling: 128x128 block tile, KTILE=16, double-buffered
#define KTILE 16
#define ASTR  20          // A smem stride (floats): 128 rows x 16 k (+pad)
#define BTSTR 20          // B smem stride (trans, [n][k])
#define BSTR  132         // B smem stride (non-trans, [k][n])
#define ATILE (128*ASTR)      // 2560 floats
#define BTILE (128*BTSTR)     // 2560 floats (>= 16*BSTR=2112)
#define EPIOFF (2*ATILE + 2*BTILE)   // 10240 floats
#define SMEMSZ ((EPIOFF + 8*256)*4)  // 49152 bytes

// ---------------- scratch (static device arrays; no allocation) --------------
__device__ float g_xbuf[MMR*DDIM];   // residual stream x
__device__ float g_gin [MMR*DDIM];   // gru_in (LN output)
__device__ float g_k   [MMR*DDIM];   // k -> c  (also dwconv + mlp_in scratch)
__device__ float g_a   [MMR*DDIM];   // a -> v
__device__ float g_h1  [MMR*HH];     // MLP hidden
__device__ float g_P [BB*DDIM*NCH];
__device__ float g_V [BB*DDIM*NCH];
__device__ float g_Hi[BB*DDIM*NCH];

// ---------------- depthwise causal conv (K=4, cross-correlation) -------------
__global__ void dwconv_kernel(const float* __restrict__ x,
                              const float* __restrict__ w,
                              const float* __restrict__ wb,
                              float* __restrict__ out)
{
    int idx = blockIdx.x * blockDim.x + threadIdx.x;   // b*S*D + s*D + c
    if (idx >= MMR*DDIM) return;
    int c = idx % DDIM;
    int bs = idx / DDIM;
    int s = bs % SS;
    float acc = wb[c];
    #pragma unroll
    for (int k = 0; k < 4; k++) {
        int sp = s + k - 3;
        if (sp >= 0) acc += w[c*4 + k] * x[idx + (k-3)*DDIM];
    }
    out[idx] = acc;
}

// ---------------- TF32 tensor-core GEMM, 128x128x16, 8 warps -----------------
// C[m,n] = sum_k A[m,k]*B(k,n);   TRANSB: B stored [N,K] (B[n*K+k])
__device__ __forceinline__ void cpasync16(float* dst, const float* src)
{
    unsigned int d = (unsigned int)__cvta_generic_to_shared(dst);
    asm volatile("cp.async.cg.shared.global [%0], [%1], 16;\n" :: "r"(d), "l"(src));
}

template<bool TRANSB>
__global__ void __launch_bounds__(256, 2)
tgemm_kernel(const float* __restrict__ A, const float* __restrict__ B,
             float* __restrict__ C, int M, int N, int K,
             const float* __restrict__ bias, const float* __restrict__ resid,
             int dorelu)
{
    extern __shared__ float sm[];
    float* Asm[2] = { sm, sm + ATILE };
    float* Bsm[2] = { sm + 2*ATILE, sm + 2*ATILE + BTILE };

    const int tid = threadIdx.x;
    const int wid = tid >> 5;
    const int lane = tid & 31;
    const int bm = blockIdx.y * 128;
    const int bn = blockIdx.x * 128;
    const int wm = (wid >> 2) * 64;   // warp grid 2(m) x 4(n)
    const int wn = (wid & 3) * 32;
    float* wbuf = sm + EPIOFF + wid*256;   // per-warp 16x16 epilogue staging

    wmma::fragment<wmma::accumulator, 16, 16, 8, float> acc[4][2];
    #pragma unroll
    for (int i = 0; i < 4; i++)
        #pragma unroll
        for (int j = 0; j < 2; j++) wmma::fill_fragment(acc[i][j], 0.f);

    // ---- tile loaders (cp.async): 512 float4 each -> 2 per thread ----
    auto loadA = [&](int buf, int k0) {
        #pragma unroll
        for (int i = 0; i < 2; i++) {
            int idx = tid + i*256;          // 128 rows x 4 f4
            int r = idx >> 2, c4 = (idx & 3) * 4;
            cpasync16(Asm[buf] + r*ASTR + c4, A + (size_t)(bm + r)*K + k0 + c4);
        }
    };
    auto loadB = [&](int buf, int k0) {
        if (TRANSB) {
            #pragma unroll
            for (int i = 0; i < 2; i++) {
                int idx = tid + i*256;      // 128 rows (n) x 4 f4 (k)
                int r = idx >> 2, c4 = (idx & 3) * 4;
                cpasync16(Bsm[buf] + r*BTSTR + c4, B + (size_t)(bn + r)*K + k0 + c4);
            }
        } else {
            #pragma unroll
            for (int i = 0; i < 2; i++) {
                int idx = tid + i*256;      // 16 rows (k) x 32 f4 (n)
                int r = idx >> 5, c4 = (idx & 31) * 4;
                cpasync16(Bsm[buf] + r*BSTR + c4, B + (size_t)(k0 + r)*N + bn + c4);
            }
        }
    };

    const int nk = K / KTILE;
    loadA(0, 0); loadB(0, 0);
    asm volatile("cp.async.commit_group;\n");

    for (int kt = 0; kt < nk; kt++) {
        if (kt + 1 < nk) {
            loadA((kt+1)&1, (kt+1)*KTILE);
            loadB((kt+1)&1, (kt+1)*KTILE);
            asm volatile("cp.async.commit_group;\n");
            asm volatile("cp.async.wait_group 1;\n");
        } else {
            asm volatile("cp.async.wait_group 0;\n");
        }
        __syncthreads();

        const float* a = Asm[kt&1];
        const float* b = Bsm[kt&1];
        // NOTE: no __float_to_tf32 — HMMA.tf32 truncates mantissa in HW.
        #pragma unroll
        for (int ks = 0; ks < 2; ks++) {
            const int kk = ks * 8;
            wmma::fragment<wmma::matrix_a, 16, 16, 8, wmma::precision::tf32, wmma::row_major> af[4];
            #pragma unroll
            for (int i = 0; i < 4; i++)
                wmma::load_matrix_sync(af[i], a + (wm + i*16)*ASTR + kk, ASTR);
            if constexpr (TRANSB) {
                wmma::fragment<wmma::matrix_b, 16, 16, 8, wmma::precision::tf32, wmma::col_major> bf[2];
                #pragma unroll
                for (int j = 0; j < 2; j++)
                    wmma::load_matrix_sync(bf[j], b + (wn + j*16)*BTSTR + kk, BTSTR);
                #pragma unroll
                for (int i = 0; i < 4; i++)
                    #pragma unroll
                    for (int j = 0; j < 2; j++)
                        wmma::mma_sync(acc[i][j], af[i], bf[j], acc[i][j]);
            } else {
                wmma::fragment<wmma::matrix_b, 16, 16, 8, wmma::precision::tf32, wmma::row_major> bf[2];
                #pragma unroll
                for (int j = 0; j < 2; j++)
                    wmma::load_matrix_sync(bf[j], b + kk*BSTR + wn + j*16, BSTR);
                #pragma unroll
                for (int i = 0; i < 4; i++)
                    #pragma unroll
                    for (int j = 0; j < 2; j++)
                        wmma::mma_sync(acc[i][j], af[i], bf[j], acc[i][j]);
            }
        }
        __syncthreads();
    }

    // ---- epilogue: per-warp 16x16 staging, fused bias/relu/resid ----
    #pragma unroll
    for (int i = 0; i < 4; i++) {
        #pragma unroll
        for (int j = 0; j < 2; j++) {
            wmma::store_matrix_sync(wbuf, acc[i][j], 16, wmma::mem_row_major);
            __syncwarp();
            // 256 floats: each lane handles 8 consecutive (r = lane/2, c = (lane&1)*8)
            int r = lane >> 1, c = (lane & 1) * 8;
            int row = bm + wm + i*16 + r;
            int col = bn + wn + j*16 + c;
            float4 v0 = *(float4*)&wbuf[r*16 + c];
            float4 v1 = *(float4*)&wbuf[r*16 + c + 4];
            if (bias) {
                float4 b0 = *(const float4*)&bias[col];
                float4 b1 = *(const float4*)&bias[col+4];
                v0.x += b0.x; v0.y += b0.y; v0.z += b0.z; v0.w += b0.w;
                v1.x += b1.x; v1.y += b1.y; v1.z += b1.z; v1.w += b1.w;
            }
            if (dorelu) {
                v0.x = fmaxf(v0.x, 0.f); v0.y = fmaxf(v0.y, 0.f);
                v0.z = fmaxf(v0.z, 0.f); v0.w = fmaxf(v0.w, 0.f);
                v1.x = fmaxf(v1.x, 0.f); v1.y = fmaxf(v1.y, 0.f);
                v1.z = fmaxf(v1.z, 0.f); v1.w = fmaxf(v1.w, 0.f);
            }
            if (resid) {
                float4 r0 = *(const float4*)&resid[(size_t)row*N + col];
                float4 r1 = *(const float4*)&resid[(size_t)row*N + col + 4];
                v0.x += r0.x; v0.y += r0.y; v0.z += r0.z; v0.w += r0.w;
                v1.x += r1.x; v1.y += r1.y; v1.z += r1.z; v1.w += r1.w;
            }
            *(float4*)&C[(size_t)row*N + col]     = v0;
            *(float4*)&C[(size_t)row*N + col + 4] = v1;
            __syncwarp();
        }
    }
}

// ---------------- LayerNorm over last dim (512), warp-per-row ---------------
__global__ void ln_kernel(const float* __restrict__ in, float* __restrict__ out,
                          const float* __restrict__ g, const float* __restrict__ b)
{
    int warp = threadIdx.x >> 5, lane = threadIdx.x & 31;
    int row = blockIdx.x * 8 + warp;
    const float* p = in + (size_t)row * DDIM;
    float vals[16];
    float s = 0.f;
    #pragma unroll
    for (int i = 0; i < 16; i++) { vals[i] = p[lane + i*32]; s += vals[i]; }
    #pragma unroll
    for (int o = 16; o > 0; o >>= 1) s += __shfl_xor_sync(0xffffffff, s, o);
    float mean = s * (1.f/DDIM);
    float vs = 0.f;
    #pragma unroll
    for (int i = 0; i < 16; i++) { float d = vals[i]-mean; vs += d*d; }
    #pragma unroll
    for (int o = 16; o > 0; o >>= 1) vs += __shfl_xor_sync(0xffffffff, vs, o);
    float inv = rsqrtf(vs * (1.f/DDIM) + 1e-5f);
    float* q = out + (size_t)row * DDIM;
    #pragma unroll
    for (int i = 0; i < 16; i++) {
        int c = lane + i*32;
        q[c] = (vals[i]-mean) * inv * g[c] + b[c];
    }
}

// ---------------- scan pass1 (fused gating): k,a -> c,v ; chunk carries -----
__global__ void scan_pass1(float* __restrict__ kb, float* __restrict__ ab,
                           float* __restrict__ Pb, float* __restrict__ Vb)
{
    int gid = blockIdx.x * blockDim.x + threadIdx.x;   // b*(NCH*D) + chunk*D + d
    int b = gid / (DDIM*NCH);
    int r = gid - b*(DDIM*NCH);
    int chunk = r / DDIM;
    int d = r - chunk*DDIM;
    size_t base = ((size_t)b*SS + (size_t)chunk*CHK)*DDIM + d;
    float p = 1.f, v = 0.f;
    for (int i = 0; i < CHK; i++) {
        size_t o = base + (size_t)i*DDIM;
        float k = kb[o];
        float a = ab[o];
        float e = __expf(k);
        float ci = 1.f / (1.f + e);           // sigmoid(-k)
        float zi = e * ci;                    // sigmoid(k)
        float gg = (a >= 0.f) ? (a + 0.5f) : (1.f / (1.f + __expf(-a)));
        float vi = zi * gg;
        kb[o] = ci;
        ab[o] = vi;
        v = fmaf(ci, v, vi);
        p *= ci;
    }
    int ch = (b*DDIM + d)*NCH + chunk;
    Pb[ch] = p; Vb[ch] = v;
}

// pass2: per-channel serial scan over 32 chunk carries
__global__ void scan_pass2(const float* __restrict__ Pb, const float* __restrict__ Vb,
                           float* __restrict__ Hib)
{
    int ch = blockIdx.x * blockDim.x + threadIdx.x;    // 0..B*D-1
    if (ch >= BB*DDIM) return;
    float h = 0.5f;
    #pragma unroll
    for (int c = 0; c < NCH; c++) {
        Hib[ch*NCH + c] = h;
        h = fmaf(Pb[ch*NCH + c], h, Vb[ch*NCH + c]);
    }
}

// pass3: re-scan applying carry, x += h (in place on xbuf)
__global__ void scan_pass3(const float* __restrict__ cb, const float* __restrict__ vb,
                           const float* __restrict__ Hib, float* __restrict__ xb)
{
    int gid = blockIdx.x * blockDim.x + threadIdx.x;
    int b = gid / (DDIM*NCH);
    int r = gid - b*(DDIM*NCH);
    int chunk = r / DDIM;
    int d = r - chunk*DDIM;
    size_t base = ((size_t)b*SS + (size_t)chunk*CHK)*DDIM + d;
    float h = Hib[(b*DDIM + d)*NCH + chunk];
    for (int i = 0; i < CHK; i++) {
        size_t o = base + (size_t)i*DDIM;
        h = fmaf(cb[o], h, vb[o]);
        xb[o] += h;
    }
}

// -------------------------------- launch ------------------------------------
extern "C" void kernel_launch(void* const* d_in, const int* in_sizes, int n_in,
                              void* d_out, int out_size)
{
    const float* x     = (const float*)d_in[0];
    const float* dw_w  = (const float*)d_in[1];
    const float* dw_b  = (const float*)d_in[2];
    const float* pw_w  = (const float*)d_in[3];
    const float* pw_b  = (const float*)d_in[4];
    const float* ln1_g = (const float*)d_in[5];
    const float* ln1_b = (const float*)d_in[6];
    const float* Wz    = (const float*)d_in[7];
    const float* Wh    = (const float*)d_in[8];
    const float* lng   = (const float*)d_in[9];
    const float* lnb   = (const float*)d_in[10];
    const float* ln2_g = (const float*)d_in[11];
    const float* ln2_b = (const float*)d_in[12];
    const float* W1    = (const float*)d_in[13];
    const float* b1    = (const float*)d_in[14];
    const float* W2    = (const float*)d_in[15];
    const float* b2    = (const float*)d_in[16];
    float* out = (float*)d_out;

    float *xbuf, *gin, *kb, *ab, *hb, *Pb, *Vb, *Hib;
    cudaGetSymbolAddress((void**)&xbuf, g_xbuf);
    cudaGetSymbolAddress((void**)&gin,  g_gin);
    cudaGetSymbolAddress((void**)&kb,   g_k);
    cudaGetSymbolAddress((void**)&ab,   g_a);
    cudaGetSymbolAddress((void**)&hb,   g_h1);
    cudaGetSymbolAddress((void**)&Pb,   g_P);
    cudaGetSymbolAddress((void**)&Vb,   g_V);
    cudaGetSymbolAddress((void**)&Hib,  g_Hi);

    cudaFuncSetAttribute(tgemm_kernel<true>,
        cudaFuncAttributeMaxDynamicSharedMemorySize, SMEMSZ);
    cudaFuncSetAttribute(tgemm_kernel<false>,
        cudaFuncAttributeMaxDynamicSharedMemorySize, SMEMSZ);

    const int NELT = MMR*DDIM;
    dim3 eltGrid((NELT + 255)/256);

    // 1) depthwise conv -> kb
    dwconv_kernel<<<eltGrid, 256>>>(x, dw_w, dw_b, kb);

    // 2) pointwise conv (B = pw_w[o,c] transposed) + pw_b + residual x -> xbuf
    tgemm_kernel<true><<<dim3(DDIM/128, MMR/128), 256, SMEMSZ>>>(
        kb, pw_w, xbuf, MMR, DDIM, DDIM, pw_b, x, 0);

    // 3) gru_in = LN(xbuf, ln1)
    ln_kernel<<<MMR/8, 256>>>(xbuf, gin, ln1_g, ln1_b);

    // 4) GRU layers
    for (int l = 0; l < LL; l++) {
        tgemm_kernel<false><<<dim3(DDIM/128, MMR/128), 256, SMEMSZ>>>(
            gin, Wz + (size_t)l*DDIM*DDIM, kb, MMR, DDIM, DDIM, nullptr, nullptr, 0);
        tgemm_kernel<false><<<dim3(DDIM/128, MMR/128), 256, SMEMSZ>>>(
            gin, Wh + (size_t)l*DDIM*DDIM, ab, MMR, DDIM, DDIM, nullptr, nullptr, 0);
        scan_pass1<<<(BB*DDIM*NCH)/256, 256>>>(kb, ab, Pb, Vb);
        scan_pass2<<<(BB*DDIM + 255)/256, 256>>>(Pb, Vb, Hib);
        scan_pass3<<<(BB*DDIM*NCH)/256, 256>>>(kb, ab, Hib, xbuf);
        ln_kernel<<<MMR/8, 256>>>(xbuf, gin, lng + l*DDIM, lnb + l*DDIM);
    }

    // 5) mlp_in = LN(gin, ln2) -> kb
    ln_kernel<<<MMR/8, 256>>>(gin, kb, ln2_g, ln2_b);

    // 6) hidden = relu(mlp_in @ W1 + b1) -> hb
    tgemm_kernel<false><<<dim3(HH/128, MMR/128), 256, SMEMSZ>>>(
        kb, W1, hb, MMR, HH, DDIM, b1, nullptr, 1);

    // 7) out = hidden @ W2 + b2 + xbuf
    tgemm_kernel<false><<<dim3(DDIM/128, MMR/128), 256, SMEMSZ>>>(
        hb, W2, out, MMR, DDIM, HH, b2, xbuf, 0);
}